// round 5
// baseline (speedup 1.0000x reference)
#include <cuda_runtime.h>
#include <cstdint>

// Problem constants
#define BB   16384
#define AA   32
#define UU   64
#define SS   2048
#define EE   32
#define HYPD 64
#define HHD  4
#define NN   288      // H*HYP + E = 256 + 32
#define KKD  2048

#define NBLK (BB/128) // 128 gemm blocks

// ---------------- scratch (device globals; no allocation allowed) -------------
__device__ float g_Wcat[NN * KKD];      // packed+tf32-rounded weights [n][k]
__device__ float g_bias[NN];            // concatenated biases
__device__ float g_keyT[HHD * EE * UU]; // key_w transposed to [h][e][u]
__device__ float g_part[NBLK * 5];      // per-block partials: [mag, ent0..3]

__device__ __forceinline__ uint32_t f2tf(float f) {
    uint32_t u; asm("cvt.rna.tf32.f32 %0, %1;" : "=r"(u) : "f"(f)); return u;
}

__device__ __forceinline__ float warpsum(float v) {
    #pragma unroll
    for (int o = 16; o; o >>= 1) v += __shfl_xor_sync(0xffffffffu, v, o);
    return v;
}
__device__ __forceinline__ float warpmax(float v) {
    #pragma unroll
    for (int o = 16; o; o >>= 1) v = fmaxf(v, __shfl_xor_sync(0xffffffffu, v, o));
    return v;
}

// ---------------- kernel 0a: coalesced weight pack via smem transpose ---------
// z=0..3: sel_w1 head z ([2048][64] -> rows z*64..z*64+63 of Wcat)
// z=4   : v_w1 ([2048][32] -> rows 256..287 of Wcat)
__global__ __launch_bounds__(256)
void pack_transpose(const float* __restrict__ sel_w1,
                    const float* __restrict__ v_w1) {
    __shared__ float tile[32][33];
    const int z  = blockIdx.z;
    const int k0 = blockIdx.x * 32;
    const int j0 = blockIdx.y * 32;
    const int tx = threadIdx.x, ty = threadIdx.y;  // 32 x 8

    if (z == 4 && blockIdx.y != 0) return;

    if (z < 4) {
        const float* src = sel_w1 + (size_t)z * SS * HYPD;
        #pragma unroll
        for (int i = 0; i < 32; i += 8)
            tile[ty + i][tx] = src[(size_t)(k0 + ty + i) * HYPD + j0 + tx];
        __syncthreads();
        #pragma unroll
        for (int i = 0; i < 32; i += 8)
            g_Wcat[(size_t)(z * 64 + j0 + ty + i) * KKD + k0 + tx] =
                __uint_as_float(f2tf(tile[tx][ty + i]));
    } else {
        #pragma unroll
        for (int i = 0; i < 32; i += 8)
            tile[ty + i][tx] = v_w1[(size_t)(k0 + ty + i) * EE + tx];
        __syncthreads();
        #pragma unroll
        for (int i = 0; i < 32; i += 8)
            g_Wcat[(size_t)(256 + ty + i) * KKD + k0 + tx] =
                __uint_as_float(f2tf(tile[tx][ty + i]));
    }
}

// ---------------- kernel 0b: bias + key_w transpose ---------------------------
__global__ __launch_bounds__(256)
void pack_misc(const float* __restrict__ sel_b1,
               const float* __restrict__ v_b1,
               const float* __restrict__ key_w) {
    int idx = blockIdx.x * blockDim.x + threadIdx.x;
    if (idx < NN)
        g_bias[idx] = (idx < 256) ? sel_b1[idx] : v_b1[idx - 256];
    if (idx < HHD * UU * EE) {
        // key_w [h][u][e] -> g_keyT [h][e][u]
        int h = idx >> 11;
        int r = idx & 2047;
        int u = r >> 5;
        int e = r & 31;
        g_keyT[h * 2048 + e * 64 + u] = key_w[idx];
    }
}

// ---------------- kernel 1: fused GEMM + attention ---------------------------
#define BM 128
#define BKC 32
#define AST 36
#define BST 36
#define HST 292   // H1 smem row stride (292 mod 32 = 4 -> spread banks)
// mainloop smem:  As 2*128*36 + Bs 2*288*36 floats = 29952 floats (119808 B)
// epilogue smem:  hsm 128*292 = 37376, ssel 16*128 = 2048, spart 16*5 = 80
//                 -> 39504 floats = 158016 B (reuses mainloop region)
#define SMEM_FLOATS 39504

__global__ __launch_bounds__(512, 1)
void gemm_fused_kernel(const float* __restrict__ states,
                       const float* __restrict__ sel_w2,
                       const float* __restrict__ v_w2,
                       const float* __restrict__ v_b2,
                       float* __restrict__ out) {
    extern __shared__ float sm[];
    float* As = sm;                        // [2][BM][AST]
    float* Bs = sm + 2 * BM * AST;         // [2][NN][BST]

    const int t    = threadIdx.x;
    const int lane = t & 31;
    const int warp = t >> 5;               // 0..15
    const int wM   = warp & 3;
    const int wN   = warp >> 2;
    const int grp  = lane >> 2;            // 0..7
    const int tid4 = lane & 3;             // 0..3
    const int rowBase = blockIdx.x * BM;

    const int arow = t >> 2;               // 0..127
    const int ac4  = t & 3;

    float acc[2][9][4];
    #pragma unroll
    for (int i = 0; i < 2; i++)
        #pragma unroll
        for (int j = 0; j < 9; j++)
            #pragma unroll
            for (int c = 0; c < 4; c++) acc[i][j][c] = 0.f;

    float4 ap0, ap1;
    float bpre[18];

    // ---- prefetch tile 0 ----
    {
        const float* ap = states + (size_t)(rowBase + arow) * KKD + ac4 * 4;
        ap0 = *(const float4*)ap;
        ap1 = *(const float4*)(ap + 16);
        #pragma unroll
        for (int i = 0; i < 18; i++) {
            int lin = i * 512 + t;
            int n = lin >> 5, kk = lin & 31;
            bpre[i] = g_Wcat[n * KKD + kk];
        }
    }
    {
        float* a = As + arow * AST + ac4 * 4;
        a[0]  = __uint_as_float(f2tf(ap0.x));
        a[1]  = __uint_as_float(f2tf(ap0.y));
        a[2]  = __uint_as_float(f2tf(ap0.z));
        a[3]  = __uint_as_float(f2tf(ap0.w));
        a[16] = __uint_as_float(f2tf(ap1.x));
        a[17] = __uint_as_float(f2tf(ap1.y));
        a[18] = __uint_as_float(f2tf(ap1.z));
        a[19] = __uint_as_float(f2tf(ap1.w));
        #pragma unroll
        for (int i = 0; i < 18; i++) {
            int lin = i * 512 + t;
            int n = lin >> 5, kk = lin & 31;
            Bs[n * BST + kk] = bpre[i];
        }
    }
    __syncthreads();

    const int NITER = KKD / BKC;           // 64
    for (int it = 0; it < NITER; ++it) {
        const int cur = it & 1;
        if (it < NITER - 1) {
            const int k0 = (it + 1) * BKC;
            const float* ap = states + (size_t)(rowBase + arow) * KKD + k0 + ac4 * 4;
            ap0 = *(const float4*)ap;
            ap1 = *(const float4*)(ap + 16);
            #pragma unroll
            for (int i = 0; i < 18; i++) {
                int lin = i * 512 + t;
                int n = lin >> 5, kk = lin & 31;
                bpre[i] = g_Wcat[n * KKD + k0 + kk];
            }
        }
        const float* Ab = As + cur * BM * AST;
        const float* Bb = Bs + cur * NN * BST;
        #pragma unroll
        for (int kk = 0; kk < BKC; kk += 8) {
            uint32_t af[2][4];
            #pragma unroll
            for (int mt = 0; mt < 2; mt++) {
                int m0 = wM * 32 + mt * 16 + grp;
                af[mt][0] = __float_as_uint(Ab[m0 * AST + kk + tid4]);
                af[mt][1] = __float_as_uint(Ab[(m0 + 8) * AST + kk + tid4]);
                af[mt][2] = __float_as_uint(Ab[m0 * AST + kk + tid4 + 4]);
                af[mt][3] = __float_as_uint(Ab[(m0 + 8) * AST + kk + tid4 + 4]);
            }
            #pragma unroll
            for (int nt = 0; nt < 9; nt++) {
                int n0 = wN * 72 + nt * 8 + grp;
                uint32_t b0 = __float_as_uint(Bb[n0 * BST + kk + tid4]);
                uint32_t b1 = __float_as_uint(Bb[n0 * BST + kk + tid4 + 4]);
                #pragma unroll
                for (int mt = 0; mt < 2; mt++) {
                    asm volatile(
                        "mma.sync.aligned.m16n8k8.row.col.f32.tf32.tf32.f32 "
                        "{%0,%1,%2,%3}, {%4,%5,%6,%7}, {%8,%9}, {%0,%1,%2,%3};\n"
                        : "+f"(acc[mt][nt][0]), "+f"(acc[mt][nt][1]),
                          "+f"(acc[mt][nt][2]), "+f"(acc[mt][nt][3])
                        : "r"(af[mt][0]), "r"(af[mt][1]),
                          "r"(af[mt][2]), "r"(af[mt][3]),
                          "r"(b0), "r"(b1));
                }
            }
        }
        if (it < NITER - 1) {
            __syncthreads();
            const int nxt = cur ^ 1;
            float* a = As + nxt * BM * AST + arow * AST + ac4 * 4;
            a[0]  = __uint_as_float(f2tf(ap0.x));
            a[1]  = __uint_as_float(f2tf(ap0.y));
            a[2]  = __uint_as_float(f2tf(ap0.z));
            a[3]  = __uint_as_float(f2tf(ap0.w));
            a[16] = __uint_as_float(f2tf(ap1.x));
            a[17] = __uint_as_float(f2tf(ap1.y));
            a[18] = __uint_as_float(f2tf(ap1.z));
            a[19] = __uint_as_float(f2tf(ap1.w));
            float* bd = Bs + nxt * NN * BST;
            #pragma unroll
            for (int i = 0; i < 18; i++) {
                int lin = i * 512 + t;
                int n = lin >> 5, kk = lin & 31;
                bd[n * BST + kk] = bpre[i];
            }
            __syncthreads();
        }
    }

    // ============== fused epilogue: H1 -> smem, then attention ===============
    __syncthreads();                       // mainloop smem dead; reuse region
    float* hsm   = sm;                     // [BM][HST]
    float* ssel  = sm + BM * HST;          // [16][128]
    float* spart = ssel + 16 * 128;        // [16][5]

    // bias + relu -> hsm
    #pragma unroll
    for (int mt = 0; mt < 2; mt++) {
        int rl = wM * 32 + mt * 16 + grp;
        #pragma unroll
        for (int nt = 0; nt < 9; nt++) {
            int c0 = wN * 72 + nt * 8 + tid4 * 2;
            float b0 = g_bias[c0], b1 = g_bias[c0 + 1];
            hsm[rl * HST + c0]            = fmaxf(acc[mt][nt][0] + b0, 0.f);
            hsm[rl * HST + c0 + 1]        = fmaxf(acc[mt][nt][1] + b1, 0.f);
            hsm[(rl + 8) * HST + c0]      = fmaxf(acc[mt][nt][2] + b0, 0.f);
            hsm[(rl + 8) * HST + c0 + 1]  = fmaxf(acc[mt][nt][3] + b1, 0.f);
        }
    }
    __syncthreads();

    // each warp processes 8 rows
    float pmag = 0.f, pent[4] = {0.f, 0.f, 0.f, 0.f};
    const float invsq = 0.17677669529663687f;  // 1/sqrt(32)

    for (int i = 0; i < 8; i++) {
        const int rl = warp * 8 + i;
        const int b  = rowBase + rl;
        const float* hr = hsm + rl * HST;

        // selectors[h][e=lane]
        #pragma unroll
        for (int h = 0; h < 4; h++) {
            float s = 0.f;
            const float* w2h = sel_w2 + h * 64 * 32 + lane;
            #pragma unroll 8
            for (int k = 0; k < 64; k++)
                s += hr[h * 64 + k] * w2h[k * 32];
            ssel[warp * 128 + h * 32 + lane] = s;
        }
        __syncwarp();

        // v output
        {
            float vp = hr[256 + lane] * v_w2[lane];
            vp = warpsum(vp);
            if (lane == 0) out[(size_t)BB * AA + b] = vp + v_b2[0];
        }

        // m[h][u]: lane holds u=lane, u=lane+32
        float m0[4], m1[4];
        #pragma unroll
        for (int h = 0; h < 4; h++) {
            float a0 = 0.f, a1 = 0.f;
            const float* kh = g_keyT + h * 2048 + lane;
            const float* sw = ssel + warp * 128 + h * 32;
            #pragma unroll 8
            for (int e = 0; e < 32; e++) {
                float se = sw[e];
                a0 += kh[e * 64] * se;
                a1 += kh[e * 64 + 32] * se;
            }
            m0[h] = a0; m1[h] = a1;
        }

        // state row (mostly L2-hot: this block streamed it during mainloop)
        const float* srow = states + (size_t)b * SS;
        float v0[32], v1[32];
        #pragma unroll
        for (int a = 0; a < 32; a++) {
            v0[a] = srow[a * 64 + lane];
            v1[a] = srow[a * 64 + 32 + lane];
        }

        // logits via butterfly transpose-reduce; lane a ends with logits[h][a]
        float lg[4];
        #pragma unroll
        for (int h = 0; h < 4; h++) {
            float vals[32];
            #pragma unroll
            for (int a = 0; a < 32; a++)
                vals[a] = v0[a] * m0[h] + v1[a] * m1[h];
            #pragma unroll
            for (int m = 16; m >= 1; m >>= 1) {
                #pragma unroll
                for (int jj = 0; jj < m; jj++) {
                    float lo = vals[jj], hi = vals[jj + m];
                    float send = (lane & m) ? lo : hi;
                    float recv = __shfl_xor_sync(0xffffffffu, send, m);
                    vals[jj] = ((lane & m) ? hi : lo) + recv;
                }
            }
            lg[h] = vals[0];
        }

        // softmax + stats (lane == agent)
        float ha = 0.f, maglane = 0.f;
        #pragma unroll
        for (int h = 0; h < 4; h++) {
            maglane += lg[h] * lg[h];
            float z = lg[h] * invsq;
            float mx = warpmax(z);
            float e = __expf(z - mx);
            float ssum = warpsum(e);
            float wgt = e / ssum;
            ha += wgt;
            pent[h] += warpsum(wgt * __logf(wgt + 1e-8f));
        }
        pmag += warpsum(maglane);

        out[(size_t)b * AA + lane] = ha;  // head_attend
        __syncwarp();
    }

    if (lane == 0) {
        spart[warp * 5 + 0] = pmag;
        #pragma unroll
        for (int h = 0; h < 4; h++) spart[warp * 5 + 1 + h] = pent[h];
    }
    __syncthreads();
    if (t == 0) {
        float accp[5] = {0, 0, 0, 0, 0};
        for (int ww = 0; ww < 16; ww++)
            #pragma unroll
            for (int c = 0; c < 5; c++) accp[c] += spart[ww * 5 + c];
        #pragma unroll
        for (int c = 0; c < 5; c++) g_part[blockIdx.x * 5 + c] = accp[c];
    }
}

// ---------------- kernel 3: deterministic finalize ---------------------------
__global__ __launch_bounds__(256)
void finalize_kernel(float* __restrict__ out) {
    __shared__ float red[8][5];
    const int t = threadIdx.x, lane = t & 31, w = t >> 5;
    float acc[5] = {0, 0, 0, 0, 0};
    for (int j = t; j < NBLK; j += 256) {
        #pragma unroll
        for (int c = 0; c < 5; c++) acc[c] += g_part[j * 5 + c];
    }
    #pragma unroll
    for (int c = 0; c < 5; c++) acc[c] = warpsum(acc[c]);
    if (lane == 0)
        #pragma unroll
        for (int c = 0; c < 5; c++) red[w][c] = acc[c];
    __syncthreads();
    if (t == 0) {
        float fin[5] = {0, 0, 0, 0, 0};
        #pragma unroll
        for (int ww = 0; ww < 8; ww++)
            #pragma unroll
            for (int c = 0; c < 5; c++) fin[c] += red[ww][c];
        out[(size_t)BB * AA + BB] = 1e-3f * fin[0] / (float)((size_t)BB * AA);
        #pragma unroll
        for (int c = 1; c < 5; c++)
            out[(size_t)BB * AA + BB + c] = -fin[c] / (float)BB;
    }
}

// ---------------- launch ------------------------------------------------------
extern "C" void kernel_launch(void* const* d_in, const int* in_sizes, int n_in,
                              void* d_out, int out_size) {
    (void)in_sizes; (void)n_in; (void)out_size;
    // metadata order: agent_qs, states, sel_w1, sel_b1, sel_w2, key_w, v_w1, v_b1, v_w2, v_b2
    const float* states = (const float*)d_in[1];
    const float* sel_w1 = (const float*)d_in[2];
    const float* sel_b1 = (const float*)d_in[3];
    const float* sel_w2 = (const float*)d_in[4];
    const float* key_w  = (const float*)d_in[5];
    const float* v_w1   = (const float*)d_in[6];
    const float* v_b1   = (const float*)d_in[7];
    const float* v_w2   = (const float*)d_in[8];
    const float* v_b2   = (const float*)d_in[9];
    float* out = (float*)d_out;

    const int smem = SMEM_FLOATS * (int)sizeof(float);  // 158016
    cudaFuncSetAttribute(gemm_fused_kernel, cudaFuncAttributeMaxDynamicSharedMemorySize, smem);

    pack_transpose<<<dim3(SS / 32, 2, 5), dim3(32, 8)>>>(sel_w1, v_w1);
    pack_misc<<<(HHD * UU * EE + 255) / 256, 256>>>(sel_b1, v_b1, key_w);
    gemm_fused_kernel<<<NBLK, 512, smem>>>(states, sel_w2, v_w2, v_b2, out);
    finalize_kernel<<<1, 256>>>(out);
}

// round 6
// speedup vs baseline: 1.1872x; 1.1872x over previous
#include <cuda_runtime.h>
#include <cstdint>

// Problem constants
#define BB   16384
#define AA   32
#define UU   64
#define SS   2048
#define EE   32
#define HYPD 64
#define HHD  4
#define NN   288      // H*HYP + E = 256 + 32
#define KKD  2048

#define NB3  (BB/8)   // attn kernel blocks (8 rows per block)

// ---------------- scratch (device globals; no allocation allowed) -------------
__device__ float g_Wcat[NN * KKD];      // packed+tf32-rounded weights [n][k]
__device__ float g_bias[NN];            // concatenated biases
__device__ float g_H1[BB * NN];         // relu(states@Wcat + bias)
__device__ float g_keyT[HHD * EE * UU]; // key_w transposed to [h][e][u]
__device__ float g_part[NB3 * 5];       // per-block partials: [mag, ent0..3]

__device__ __forceinline__ uint32_t f2tf(float f) {
    uint32_t u; asm("cvt.rna.tf32.f32 %0, %1;" : "=r"(u) : "f"(f)); return u;
}

__device__ __forceinline__ float warpsum(float v) {
    #pragma unroll
    for (int o = 16; o; o >>= 1) v += __shfl_xor_sync(0xffffffffu, v, o);
    return v;
}
__device__ __forceinline__ float warpmax(float v) {
    #pragma unroll
    for (int o = 16; o; o >>= 1) v = fmaxf(v, __shfl_xor_sync(0xffffffffu, v, o));
    return v;
}

__device__ __forceinline__ uint32_t smem_u32(const void* p) {
    return (uint32_t)__cvta_generic_to_shared(p);
}
__device__ __forceinline__ void cp_async16(uint32_t dst, const void* src) {
    asm volatile("cp.async.ca.shared.global [%0], [%1], 16;\n" :: "r"(dst), "l"(src));
}
__device__ __forceinline__ void cp_commit() {
    asm volatile("cp.async.commit_group;\n");
}
template <int N>
__device__ __forceinline__ void cp_wait() {
    asm volatile("cp.async.wait_group %0;\n" :: "n"(N));
}

// ---------------- kernel 0a: coalesced weight pack via smem transpose ---------
// z=0..3: sel_w1 head z ([2048][64] -> rows z*64..z*64+63 of Wcat)
// z=4   : v_w1 ([2048][32] -> rows 256..287 of Wcat)
__global__ __launch_bounds__(256)
void pack_transpose(const float* __restrict__ sel_w1,
                    const float* __restrict__ v_w1) {
    __shared__ float tile[32][33];
    const int z  = blockIdx.z;
    const int k0 = blockIdx.x * 32;
    const int j0 = blockIdx.y * 32;
    const int tx = threadIdx.x, ty = threadIdx.y;  // 32 x 8

    if (z == 4 && blockIdx.y != 0) return;

    if (z < 4) {
        const float* src = sel_w1 + (size_t)z * SS * HYPD;
        #pragma unroll
        for (int i = 0; i < 32; i += 8)
            tile[ty + i][tx] = src[(size_t)(k0 + ty + i) * HYPD + j0 + tx];
        __syncthreads();
        #pragma unroll
        for (int i = 0; i < 32; i += 8)
            g_Wcat[(size_t)(z * 64 + j0 + ty + i) * KKD + k0 + tx] =
                __uint_as_float(f2tf(tile[tx][ty + i]));
    } else {
        #pragma unroll
        for (int i = 0; i < 32; i += 8)
            tile[ty + i][tx] = v_w1[(size_t)(k0 + ty + i) * EE + tx];
        __syncthreads();
        #pragma unroll
        for (int i = 0; i < 32; i += 8)
            g_Wcat[(size_t)(256 + ty + i) * KKD + k0 + tx] =
                __uint_as_float(f2tf(tile[tx][ty + i]));
    }
}

// ---------------- kernel 0b: bias + key_w transpose ---------------------------
__global__ __launch_bounds__(256)
void pack_misc(const float* __restrict__ sel_b1,
               const float* __restrict__ v_b1,
               const float* __restrict__ key_w) {
    int idx = blockIdx.x * blockDim.x + threadIdx.x;
    if (idx < NN)
        g_bias[idx] = (idx < 256) ? sel_b1[idx] : v_b1[idx - 256];
    if (idx < HHD * UU * EE) {
        // key_w [h][u][e] -> g_keyT [h][e][u]
        int h = idx >> 11;
        int r = idx & 2047;
        int u = r >> 5;
        int e = r & 31;
        g_keyT[h * 2048 + e * 64 + u] = key_w[idx];
    }
}

// ---------------- kernel 1: GEMM [16384,2048]x[2048,288] tf32, cp.async x3 ----
#define BM 128
#define BKC 32
#define AST 36     // A smem row stride (floats); 36*4=144B, 16B-aligned rows
#define BST 36
#define STAGES 3
#define A_STG (BM * AST)    // 4608 floats
#define B_STG (NN * BST)    // 10368 floats
#define STG_FLOATS (A_STG + B_STG)             // 14976
#define GEMM_SMEM (STAGES * STG_FLOATS * 4)    // 179712 bytes

__global__ __launch_bounds__(512, 1)
void gemm_kernel(const float* __restrict__ states) {
    extern __shared__ float sm[];
    float* As = sm;                          // [STAGES][BM][AST]
    float* Bs = sm + STAGES * A_STG;         // [STAGES][NN][BST]

    const int t    = threadIdx.x;
    const int lane = t & 31;
    const int warp = t >> 5;               // 0..15
    const int wM   = warp & 3;
    const int wN   = warp >> 2;
    const int grp  = lane >> 2;            // 0..7
    const int tid4 = lane & 3;             // 0..3
    const int rowBase = blockIdx.x * BM;

    float acc[2][9][4];
    #pragma unroll
    for (int i = 0; i < 2; i++)
        #pragma unroll
        for (int j = 0; j < 9; j++)
            #pragma unroll
            for (int c = 0; c < 4; c++) acc[i][j][c] = 0.f;

    // ---- async stage loader: A 1024 chunks of 16B, B 2304 chunks of 16B ----
    auto load_stage = [&](int s, int k0) {
        // A: 2 chunks per thread
        {
            uint32_t dstA = smem_u32(As + s * A_STG);
            #pragma unroll
            for (int r = 0; r < 2; r++) {
                int c = t + r * 512;            // 0..1023
                int arow = c >> 3;
                int koff = (c & 7) * 4;
                cp_async16(dstA + (uint32_t)(arow * AST + koff) * 4,
                           states + (size_t)(rowBase + arow) * KKD + k0 + koff);
            }
        }
        // B: 2304 chunks, 4-5 per thread
        {
            uint32_t dstB = smem_u32(Bs + s * B_STG);
            for (int c = t; c < NN * 8; c += 512) {
                int n = c >> 3;
                int koff = (c & 7) * 4;
                cp_async16(dstB + (uint32_t)(n * BST + koff) * 4,
                           g_Wcat + (size_t)n * KKD + k0 + koff);
            }
        }
        cp_commit();
    };

    // prefill 2 stages
    load_stage(0, 0);
    load_stage(1, BKC);

    const int NITER = KKD / BKC;           // 64
    for (int it = 0; it < NITER; ++it) {
        const int cur = it % STAGES;
        cp_wait<1>();          // oldest outstanding group (stage `cur`) done
        __syncthreads();       // also guarantees compute(it-1) finished

        if (it + STAGES - 1 < NITER)
            load_stage((it + 2) % STAGES, (it + 2) * BKC);

        const float* Ab = As + cur * A_STG;
        const float* Bb = Bs + cur * B_STG;
        #pragma unroll
        for (int kk = 0; kk < BKC; kk += 8) {
            uint32_t af[2][4];
            #pragma unroll
            for (int mt = 0; mt < 2; mt++) {
                int m0 = wM * 32 + mt * 16 + grp;
                af[mt][0] = f2tf(Ab[m0 * AST + kk + tid4]);
                af[mt][1] = f2tf(Ab[(m0 + 8) * AST + kk + tid4]);
                af[mt][2] = f2tf(Ab[m0 * AST + kk + tid4 + 4]);
                af[mt][3] = f2tf(Ab[(m0 + 8) * AST + kk + tid4 + 4]);
            }
            #pragma unroll
            for (int nt = 0; nt < 9; nt++) {
                int n0 = wN * 72 + nt * 8 + grp;
                uint32_t b0 = __float_as_uint(Bb[n0 * BST + kk + tid4]);
                uint32_t b1 = __float_as_uint(Bb[n0 * BST + kk + tid4 + 4]);
                #pragma unroll
                for (int mt = 0; mt < 2; mt++) {
                    asm volatile(
                        "mma.sync.aligned.m16n8k8.row.col.f32.tf32.tf32.f32 "
                        "{%0,%1,%2,%3}, {%4,%5,%6,%7}, {%8,%9}, {%0,%1,%2,%3};\n"
                        : "+f"(acc[mt][nt][0]), "+f"(acc[mt][nt][1]),
                          "+f"(acc[mt][nt][2]), "+f"(acc[mt][nt][3])
                        : "r"(af[mt][0]), "r"(af[mt][1]),
                          "r"(af[mt][2]), "r"(af[mt][3]),
                        "r"(b0), "r"(b1));
                }
            }
        }
    }

    // ---- epilogue: bias + relu -> g_H1 ----
    #pragma unroll
    for (int mt = 0; mt < 2; mt++) {
        int r0 = rowBase + wM * 32 + mt * 16 + grp;
        #pragma unroll
        for (int nt = 0; nt < 9; nt++) {
            int c0 = wN * 72 + nt * 8 + tid4 * 2;
            float b0 = g_bias[c0], b1 = g_bias[c0 + 1];
            g_H1[(size_t)r0 * NN + c0]           = fmaxf(acc[mt][nt][0] + b0, 0.f);
            g_H1[(size_t)r0 * NN + c0 + 1]       = fmaxf(acc[mt][nt][1] + b1, 0.f);
            g_H1[(size_t)(r0 + 8) * NN + c0]     = fmaxf(acc[mt][nt][2] + b0, 0.f);
            g_H1[(size_t)(r0 + 8) * NN + c0 + 1] = fmaxf(acc[mt][nt][3] + b1, 0.f);
        }
    }
}

// ---------------- kernel 2: selectors -> m -> logits -> softmax -> outputs ----
// One warp per batch row; all global loads coalesced; butterfly transpose-reduce.
__global__ __launch_bounds__(256)
void attn_kernel(const float* __restrict__ states,
                 const float* __restrict__ sel_w2,
                 const float* __restrict__ v_w2,
                 const float* __restrict__ v_b2,
                 float* __restrict__ out) {
    __shared__ float hs[8][NN];
    __shared__ float sels[8][128];
    __shared__ float spart[8][5];

    const int t = threadIdx.x, lane = t & 31, w = t >> 5;
    const int b = blockIdx.x * 8 + w;

    #pragma unroll
    for (int i = 0; i < 9; i++) hs[w][i * 32 + lane] = g_H1[(size_t)b * NN + i * 32 + lane];
    __syncwarp();

    #pragma unroll
    for (int h = 0; h < 4; h++) {
        float s = 0.f;
        const float* w2h = sel_w2 + h * 64 * 32 + lane;
        #pragma unroll 8
        for (int k = 0; k < 64; k++)
            s += hs[w][h * 64 + k] * w2h[k * 32];
        sels[w][h * 32 + lane] = s;
    }
    __syncwarp();

    {
        float vp = hs[w][256 + lane] * v_w2[lane];
        vp = warpsum(vp);
        if (lane == 0) out[(size_t)BB * AA + b] = vp + v_b2[0];
    }

    float m0[4], m1[4];
    #pragma unroll
    for (int h = 0; h < 4; h++) {
        float a0 = 0.f, a1 = 0.f;
        const float* kh = g_keyT + h * 2048 + lane;
        #pragma unroll 8
        for (int e = 0; e < 32; e++) {
            float se = sels[w][h * 32 + e];
            a0 += kh[e * 64] * se;
            a1 += kh[e * 64 + 32] * se;
        }
        m0[h] = a0; m1[h] = a1;
    }

    const float* srow = states + (size_t)b * SS;
    float v0[32], v1[32];
    #pragma unroll
    for (int a = 0; a < 32; a++) {
        v0[a] = srow[a * 64 + lane];
        v1[a] = srow[a * 64 + 32 + lane];
    }

    float lg[4];
    #pragma unroll
    for (int h = 0; h < 4; h++) {
        float vals[32];
        #pragma unroll
        for (int a = 0; a < 32; a++)
            vals[a] = v0[a] * m0[h] + v1[a] * m1[h];
        #pragma unroll
        for (int m = 16; m >= 1; m >>= 1) {
            #pragma unroll
            for (int jj = 0; jj < m; jj++) {
                float lo = vals[jj], hi = vals[jj + m];
                float send = (lane & m) ? lo : hi;
                float recv = __shfl_xor_sync(0xffffffffu, send, m);
                vals[jj] = ((lane & m) ? hi : lo) + recv;
            }
        }
        lg[h] = vals[0];
    }

    const float invsq = 0.17677669529663687f;  // 1/sqrt(32)
    float ha = 0.f, mag = 0.f;
    float entp[4];
    #pragma unroll
    for (int h = 0; h < 4; h++) {
        mag += lg[h] * lg[h];
        float z = lg[h] * invsq;
        float mx = warpmax(z);
        float e = __expf(z - mx);
        float ssum = warpsum(e);
        float wgt = e / ssum;
        ha += wgt;
        entp[h] = warpsum(wgt * __logf(wgt + 1e-8f));
    }
    mag = warpsum(mag);

    out[(size_t)b * AA + lane] = ha;  // head_attend

    if (lane == 0) {
        spart[w][0] = mag;
        #pragma unroll
        for (int h = 0; h < 4; h++) spart[w][1 + h] = entp[h];
    }
    __syncthreads();
    if (t == 0) {
        float acc[5] = {0, 0, 0, 0, 0};
        for (int ww = 0; ww < 8; ww++)
            #pragma unroll
            for (int c = 0; c < 5; c++) acc[c] += spart[ww][c];
        #pragma unroll
        for (int c = 0; c < 5; c++) g_part[blockIdx.x * 5 + c] = acc[c];
    }
}

// ---------------- kernel 3: deterministic finalize (single pass) --------------
__global__ __launch_bounds__(256)
void finalize_kernel(float* __restrict__ out) {
    __shared__ float red[8][5];
    const int t = threadIdx.x, lane = t & 31, w = t >> 5;
    float acc[5] = {0, 0, 0, 0, 0};
    for (int j = t; j < NB3; j += 256) {
        #pragma unroll
        for (int c = 0; c < 5; c++) acc[c] += g_part[j * 5 + c];
    }
    #pragma unroll
    for (int c = 0; c < 5; c++) acc[c] = warpsum(acc[c]);
    if (lane == 0)
        #pragma unroll
        for (int c = 0; c < 5; c++) red[w][c] = acc[c];
    __syncthreads();
    if (t == 0) {
        float fin[5] = {0, 0, 0, 0, 0};
        #pragma unroll
        for (int ww = 0; ww < 8; ww++)
            #pragma unroll
            for (int c = 0; c < 5; c++) fin[c] += red[ww][c];
        out[(size_t)BB * AA + BB] = 1e-3f * fin[0] / (float)((size_t)BB * AA);
        #pragma unroll
        for (int c = 1; c < 5; c++)
            out[(size_t)BB * AA + BB + c] = -fin[c] / (float)BB;
    }
}

// ---------------- launch ------------------------------------------------------
extern "C" void kernel_launch(void* const* d_in, const int* in_sizes, int n_in,
                              void* d_out, int out_size) {
    (void)in_sizes; (void)n_in; (void)out_size;
    // metadata order: agent_qs, states, sel_w1, sel_b1, sel_w2, key_w, v_w1, v_b1, v_w2, v_b2
    const float* states = (const float*)d_in[1];
    const float* sel_w1 = (const float*)d_in[2];
    const float* sel_b1 = (const float*)d_in[3];
    const float* sel_w2 = (const float*)d_in[4];
    const float* key_w  = (const float*)d_in[5];
    const float* v_w1   = (const float*)d_in[6];
    const float* v_b1   = (const float*)d_in[7];
    const float* v_w2   = (const float*)d_in[8];
    const float* v_b2   = (const float*)d_in[9];
    float* out = (float*)d_out;

    cudaFuncSetAttribute(gemm_kernel, cudaFuncAttributeMaxDynamicSharedMemorySize, GEMM_SMEM);

    pack_transpose<<<dim3(SS / 32, 2, 5), dim3(32, 8)>>>(sel_w1, v_w1);
    pack_misc<<<(HHD * UU * EE + 255) / 256, 256>>>(sel_b1, v_b1, key_w);
    gemm_kernel<<<BB / BM, 512, GEMM_SMEM>>>(states);
    attn_kernel<<<NB3, 256>>>(states, sel_w2, v_w2, v_b2, out);
    finalize_kernel<<<1, 256>>>(out);
}

// round 7
// speedup vs baseline: 1.1902x; 1.0026x over previous
#include <cuda_runtime.h>
#include <cstdint>

// Problem constants
#define BB   16384
#define AA   32
#define UU   64
#define SS   2048
#define EE   32
#define HYPD 64
#define HHD  4
#define NN   288      // H*HYP + E = 256 + 32
#define KKD  2048

#define NB3  (BB/8)   // attn kernel blocks (8 rows per block)

// ---------------- scratch (device globals; no allocation allowed) -------------
__device__ float g_Wcat[NN * KKD];      // packed+tf32-rounded weights [n][k]
__device__ float g_bias[NN];            // concatenated biases
__device__ float g_H1[BB * NN];         // relu(states@Wcat + bias)
__device__ float g_C[HHD * HYPD * UU];  // C[h][k][u] = sum_e sel_w2[h][k][e]*key_w[h][u][e]
__device__ float g_M[BB * 256];         // M[b][h*64+u] = sum_k H1[b][h*64+k]*C[h][k][u]
__device__ float g_part[NB3 * 5];       // per-block partials: [mag, ent0..3]

__device__ __forceinline__ uint32_t f2tf(float f) {
    uint32_t u; asm("cvt.rna.tf32.f32 %0, %1;" : "=r"(u) : "f"(f)); return u;
}

__device__ __forceinline__ float warpsum(float v) {
    #pragma unroll
    for (int o = 16; o; o >>= 1) v += __shfl_xor_sync(0xffffffffu, v, o);
    return v;
}
__device__ __forceinline__ float warpmax(float v) {
    #pragma unroll
    for (int o = 16; o; o >>= 1) v = fmaxf(v, __shfl_xor_sync(0xffffffffu, v, o));
    return v;
}

__device__ __forceinline__ uint32_t smem_u32(const void* p) {
    return (uint32_t)__cvta_generic_to_shared(p);
}
__device__ __forceinline__ void cp_async16(uint32_t dst, const void* src) {
    asm volatile("cp.async.ca.shared.global [%0], [%1], 16;\n" :: "r"(dst), "l"(src));
}
__device__ __forceinline__ void cp_commit() {
    asm volatile("cp.async.commit_group;\n");
}
template <int N>
__device__ __forceinline__ void cp_wait() {
    asm volatile("cp.async.wait_group %0;\n" :: "n"(N));
}

// ---------------- kernel 0a: coalesced weight pack via smem transpose ---------
__global__ __launch_bounds__(256)
void pack_transpose(const float* __restrict__ sel_w1,
                    const float* __restrict__ v_w1) {
    __shared__ float tile[32][33];
    const int z  = blockIdx.z;
    const int k0 = blockIdx.x * 32;
    const int j0 = blockIdx.y * 32;
    const int tx = threadIdx.x, ty = threadIdx.y;  // 32 x 8

    if (z == 4 && blockIdx.y != 0) return;

    if (z < 4) {
        const float* src = sel_w1 + (size_t)z * SS * HYPD;
        #pragma unroll
        for (int i = 0; i < 32; i += 8)
            tile[ty + i][tx] = src[(size_t)(k0 + ty + i) * HYPD + j0 + tx];
        __syncthreads();
        #pragma unroll
        for (int i = 0; i < 32; i += 8)
            g_Wcat[(size_t)(z * 64 + j0 + ty + i) * KKD + k0 + tx] =
                __uint_as_float(f2tf(tile[tx][ty + i]));
    } else {
        #pragma unroll
        for (int i = 0; i < 32; i += 8)
            tile[ty + i][tx] = v_w1[(size_t)(k0 + ty + i) * EE + tx];
        __syncthreads();
        #pragma unroll
        for (int i = 0; i < 32; i += 8)
            g_Wcat[(size_t)(256 + ty + i) * KKD + k0 + tx] =
                __uint_as_float(f2tf(tile[tx][ty + i]));
    }
}

// ---------------- kernel 0b: bias -------------------------------------------
__global__ __launch_bounds__(288)
void pack_bias(const float* __restrict__ sel_b1, const float* __restrict__ v_b1) {
    int idx = threadIdx.x;
    if (idx < NN)
        g_bias[idx] = (idx < 256) ? sel_b1[idx] : v_b1[idx - 256];
}

// ---------------- kernel 0c: C[h] = sel_w2[h] @ key_w[h]^T -------------------
// one block per head; sw2/kw staged in smem
__global__ __launch_bounds__(256)
void pack_c(const float* __restrict__ sel_w2, const float* __restrict__ key_w) {
    __shared__ float sw2[HYPD * EE];   // [k][e]
    __shared__ float kw[UU * EE];      // [u][e]
    const int h = blockIdx.x;
    const int t = threadIdx.x;

    for (int i = t; i < HYPD * EE; i += 256) sw2[i] = sel_w2[h * HYPD * EE + i];
    for (int i = t; i < UU * EE; i += 256)   kw[i]  = key_w[h * UU * EE + i];
    __syncthreads();

    // 4096 outputs, 16 per thread
    for (int o = t; o < HYPD * UU; o += 256) {
        int k = o >> 6, u = o & 63;
        float s = 0.f;
        #pragma unroll
        for (int e = 0; e < EE; e++) s += sw2[k * EE + e] * kw[u * EE + e];
        g_C[h * HYPD * UU + o] = s;
    }
}

// ---------------- kernel 1: GEMM [16384,2048]x[2048,288] tf32, cp.async x3 ----
#define BM 128
#define BKC 32
#define AST 36
#define BST 36
#define STAGES 3
#define A_STG (BM * AST)    // 4608 floats
#define B_STG (NN * BST)    // 10368 floats
#define STG_FLOATS (A_STG + B_STG)             // 14976
#define GEMM_SMEM (STAGES * STG_FLOATS * 4)    // 179712 bytes

__global__ __launch_bounds__(512, 1)
void gemm_kernel(const float* __restrict__ states) {
    extern __shared__ float sm[];
    float* As = sm;
    float* Bs = sm + STAGES * A_STG;

    const int t    = threadIdx.x;
    const int lane = t & 31;
    const int warp = t >> 5;
    const int wM   = warp & 3;
    const int wN   = warp >> 2;
    const int grp  = lane >> 2;
    const int tid4 = lane & 3;
    const int rowBase = blockIdx.x * BM;

    float acc[2][9][4];
    #pragma unroll
    for (int i = 0; i < 2; i++)
        #pragma unroll
        for (int j = 0; j < 9; j++)
            #pragma unroll
            for (int c = 0; c < 4; c++) acc[i][j][c] = 0.f;

    auto load_stage = [&](int s, int k0) {
        {
            uint32_t dstA = smem_u32(As + s * A_STG);
            #pragma unroll
            for (int r = 0; r < 2; r++) {
                int c = t + r * 512;
                int arow = c >> 3;
                int koff = (c & 7) * 4;
                cp_async16(dstA + (uint32_t)(arow * AST + koff) * 4,
                           states + (size_t)(rowBase + arow) * KKD + k0 + koff);
            }
        }
        {
            uint32_t dstB = smem_u32(Bs + s * B_STG);
            for (int c = t; c < NN * 8; c += 512) {
                int n = c >> 3;
                int koff = (c & 7) * 4;
                cp_async16(dstB + (uint32_t)(n * BST + koff) * 4,
                           g_Wcat + (size_t)n * KKD + k0 + koff);
            }
        }
        cp_commit();
    };

    load_stage(0, 0);
    load_stage(1, BKC);

    const int NITER = KKD / BKC;           // 64
    for (int it = 0; it < NITER; ++it) {
        const int cur = it % STAGES;
        cp_wait<1>();
        __syncthreads();

        if (it + STAGES - 1 < NITER)
            load_stage((it + 2) % STAGES, (it + 2) * BKC);

        const float* Ab = As + cur * A_STG;
        const float* Bb = Bs + cur * B_STG;
        #pragma unroll
        for (int kk = 0; kk < BKC; kk += 8) {
            uint32_t af[2][4];
            #pragma unroll
            for (int mt = 0; mt < 2; mt++) {
                int m0 = wM * 32 + mt * 16 + grp;
                af[mt][0] = f2tf(Ab[m0 * AST + kk + tid4]);
                af[mt][1] = f2tf(Ab[(m0 + 8) * AST + kk + tid4]);
                af[mt][2] = f2tf(Ab[m0 * AST + kk + tid4 + 4]);
                af[mt][3] = f2tf(Ab[(m0 + 8) * AST + kk + tid4 + 4]);
            }
            #pragma unroll
            for (int nt = 0; nt < 9; nt++) {
                int n0 = wN * 72 + nt * 8 + grp;
                uint32_t b0 = __float_as_uint(Bb[n0 * BST + kk + tid4]);
                uint32_t b1 = __float_as_uint(Bb[n0 * BST + kk + tid4 + 4]);
                #pragma unroll
                for (int mt = 0; mt < 2; mt++) {
                    asm volatile(
                        "mma.sync.aligned.m16n8k8.row.col.f32.tf32.tf32.f32 "
                        "{%0,%1,%2,%3}, {%4,%5,%6,%7}, {%8,%9}, {%0,%1,%2,%3};\n"
                        : "+f"(acc[mt][nt][0]), "+f"(acc[mt][nt][1]),
                          "+f"(acc[mt][nt][2]), "+f"(acc[mt][nt][3])
                        : "r"(af[mt][0]), "r"(af[mt][1]),
                          "r"(af[mt][2]), "r"(af[mt][3]),
                        "r"(b0), "r"(b1));
                }
            }
        }
    }

    #pragma unroll
    for (int mt = 0; mt < 2; mt++) {
        int r0 = rowBase + wM * 32 + mt * 16 + grp;
        #pragma unroll
        for (int nt = 0; nt < 9; nt++) {
            int c0 = wN * 72 + nt * 8 + tid4 * 2;
            float b0 = g_bias[c0], b1 = g_bias[c0 + 1];
            g_H1[(size_t)r0 * NN + c0]           = fmaxf(acc[mt][nt][0] + b0, 0.f);
            g_H1[(size_t)r0 * NN + c0 + 1]       = fmaxf(acc[mt][nt][1] + b1, 0.f);
            g_H1[(size_t)(r0 + 8) * NN + c0]     = fmaxf(acc[mt][nt][2] + b0, 0.f);
            g_H1[(size_t)(r0 + 8) * NN + c0 + 1] = fmaxf(acc[mt][nt][3] + b1, 0.f);
        }
    }
}

// ---------------- kernel 1.5: M = H1 @ blockdiag(C), plus v output -----------
// 32 rows per block; C (64KB) + H1 tile staged in smem so weights amortize.
#define MROWS 32
#define HSTM 289   // hsm row stride (289 mod 32 = 1 -> conflict-free lane*289)
#define MST  257   // Ms row stride
__global__ __launch_bounds__(256)
void m_kernel(const float* __restrict__ v_w2,
              const float* __restrict__ v_b2,
              float* __restrict__ out) {
    extern __shared__ float smm[];
    float* Cs   = smm;                       // [4][64][64] = 16384
    float* hsm  = Cs + HHD * HYPD * UU;      // [32][289]   = 9248
    float* Ms   = hsm + MROWS * HSTM;        // [32][257]   = 8224
    float* vw2s = Ms + MROWS * MST;          // [32]

    const int t = threadIdx.x, lane = t & 31, w = t >> 5;   // 8 warps
    const int b0 = blockIdx.x * MROWS;

    for (int i = t; i < HHD * HYPD * UU; i += 256) Cs[i] = g_C[i];
    for (int i = t; i < MROWS * NN; i += 256) {
        int r = i / NN, c = i - r * NN;
        hsm[r * HSTM + c] = g_H1[(size_t)(b0 + r) * NN + c];
    }
    if (t < 32) vw2s[t] = v_w2[t];
    __syncthreads();

    // warp w: head h = w>>1, u-half u0 = (w&1)*32 ; lane = row
    {
        const int h  = w >> 1;
        const int u0 = (w & 1) * 32;
        float acc[32];
        #pragma unroll
        for (int j = 0; j < 32; j++) acc[j] = 0.f;

        const float* hr = hsm + lane * HSTM + h * 64;
        const float* Cb = Cs + h * HYPD * UU + u0;
        #pragma unroll 4
        for (int k = 0; k < 64; k++) {
            float hval = hr[k];
            const float4* cp4 = (const float4*)(Cb + k * UU);
            #pragma unroll
            for (int q = 0; q < 8; q++) {
                float4 cv = cp4[q];
                acc[q * 4 + 0] += hval * cv.x;
                acc[q * 4 + 1] += hval * cv.y;
                acc[q * 4 + 2] += hval * cv.z;
                acc[q * 4 + 3] += hval * cv.w;
            }
        }
        float* mrow = Ms + lane * MST + h * 64 + u0;
        #pragma unroll
        for (int j = 0; j < 32; j++) mrow[j] = acc[j];
    }

    // v output: one warp's worth of rows handled by threads 0..31
    if (t < 32) {
        float s = 0.f;
        const float* hr = hsm + t * HSTM + 256;
        #pragma unroll
        for (int j = 0; j < 32; j++) s += hr[j] * vw2s[j];
        out[(size_t)BB * AA + b0 + t] = s + v_b2[0];
    }
    __syncthreads();

    // coalesced store of the 32x256 M tile (rows contiguous in g_M)
    float* gdst = g_M + (size_t)b0 * 256;
    for (int i = t; i < MROWS * 256; i += 256) {
        int r = i >> 8, c = i & 255;
        gdst[i] = Ms[r * MST + c];
    }
}
#define M_SMEM ((HHD*HYPD*UU + MROWS*HSTM + MROWS*MST + 32) * 4)

// ---------------- kernel 2: logits -> softmax -> outputs ----------------------
// One warp per batch row. m loaded from g_M (8 coalesced loads); states
// coalesced; butterfly transpose-reduce leaves lane == agent.
__global__ __launch_bounds__(256)
void attn_kernel(const float* __restrict__ states,
                 float* __restrict__ out) {
    __shared__ float spart[8][5];

    const int t = threadIdx.x, lane = t & 31, w = t >> 5;
    const int b = blockIdx.x * 8 + w;

    // m[h][u]: lane holds u=lane and u=lane+32
    float m0[4], m1[4];
    const float* mrow = g_M + (size_t)b * 256;
    #pragma unroll
    for (int h = 0; h < 4; h++) {
        m0[h] = mrow[h * 64 + lane];
        m1[h] = mrow[h * 64 + 32 + lane];
    }

    const float* srow = states + (size_t)b * SS;
    float v0[32], v1[32];
    #pragma unroll
    for (int a = 0; a < 32; a++) {
        v0[a] = srow[a * 64 + lane];
        v1[a] = srow[a * 64 + 32 + lane];
    }

    float lg[4];
    #pragma unroll
    for (int h = 0; h < 4; h++) {
        float vals[32];
        #pragma unroll
        for (int a = 0; a < 32; a++)
            vals[a] = v0[a] * m0[h] + v1[a] * m1[h];
        #pragma unroll
        for (int m = 16; m >= 1; m >>= 1) {
            #pragma unroll
            for (int jj = 0; jj < m; jj++) {
                float lo = vals[jj], hi = vals[jj + m];
                float send = (lane & m) ? lo : hi;
                float recv = __shfl_xor_sync(0xffffffffu, send, m);
                vals[jj] = ((lane & m) ? hi : lo) + recv;
            }
        }
        lg[h] = vals[0];
    }

    const float invsq = 0.17677669529663687f;  // 1/sqrt(32)
    float ha = 0.f, mag = 0.f;
    float entp[4];
    #pragma unroll
    for (int h = 0; h < 4; h++) {
        mag += lg[h] * lg[h];
        float z = lg[h] * invsq;
        float mx = warpmax(z);
        float e = __expf(z - mx);
        float ssum = warpsum(e);
        float wgt = e / ssum;
        ha += wgt;
        entp[h] = warpsum(wgt * __logf(wgt + 1e-8f));
    }
    mag = warpsum(mag);

    out[(size_t)b * AA + lane] = ha;  // head_attend

    if (lane == 0) {
        spart[w][0] = mag;
        #pragma unroll
        for (int h = 0; h < 4; h++) spart[w][1 + h] = entp[h];
    }
    __syncthreads();
    if (t == 0) {
        float acc[5] = {0, 0, 0, 0, 0};
        for (int ww = 0; ww < 8; ww++)
            #pragma unroll
            for (int c = 0; c < 5; c++) acc[c] += spart[ww][c];
        #pragma unroll
        for (int c = 0; c < 5; c++) g_part[blockIdx.x * 5 + c] = acc[c];
    }
}

// ---------------- kernel 3: deterministic finalize ----------------------------
__global__ __launch_bounds__(256)
void finalize_kernel(float* __restrict__ out) {
    __shared__ float red[8][5];
    const int t = threadIdx.x, lane = t & 31, w = t >> 5;
    float acc[5] = {0, 0, 0, 0, 0};
    for (int j = t; j < NB3; j += 256) {
        #pragma unroll
        for (int c = 0; c < 5; c++) acc[c] += g_part[j * 5 + c];
    }
    #pragma unroll
    for (int c = 0; c < 5; c++) acc[c] = warpsum(acc[c]);
    if (lane == 0)
        #pragma unroll
        for (int c = 0; c < 5; c++) red[w][c] = acc[c];
    __syncthreads();
    if (t == 0) {
        float fin[5] = {0, 0, 0, 0, 0};
        #pragma unroll
        for (int ww = 0; ww < 8; ww++)
            #pragma unroll
            for (int c = 0; c < 5; c++) fin[c] += red[ww][c];
        out[(size_t)BB * AA + BB] = 1e-3f * fin[0] / (float)((size_t)BB * AA);
        #pragma unroll
        for (int c = 1; c < 5; c++)
            out[(size_t)BB * AA + BB + c] = -fin[c] / (float)BB;
    }
}

// ---------------- launch ------------------------------------------------------
extern "C" void kernel_launch(void* const* d_in, const int* in_sizes, int n_in,
                              void* d_out, int out_size) {
    (void)in_sizes; (void)n_in; (void)out_size;
    // metadata order: agent_qs, states, sel_w1, sel_b1, sel_w2, key_w, v_w1, v_b1, v_w2, v_b2
    const float* states = (const float*)d_in[1];
    const float* sel_w1 = (const float*)d_in[2];
    const float* sel_b1 = (const float*)d_in[3];
    const float* sel_w2 = (const float*)d_in[4];
    const float* key_w  = (const float*)d_in[5];
    const float* v_w1   = (const float*)d_in[6];
    const float* v_b1   = (const float*)d_in[7];
    const float* v_w2   = (const float*)d_in[8];
    const float* v_b2   = (const float*)d_in[9];
    float* out = (float*)d_out;

    cudaFuncSetAttribute(gemm_kernel, cudaFuncAttributeMaxDynamicSharedMemorySize, GEMM_SMEM);
    cudaFuncSetAttribute(m_kernel, cudaFuncAttributeMaxDynamicSharedMemorySize, M_SMEM);

    pack_transpose<<<dim3(SS / 32, 2, 5), dim3(32, 8)>>>(sel_w1, v_w1);
    pack_bias<<<1, 288>>>(sel_b1, v_b1);
    pack_c<<<HHD, 256>>>(sel_w2, key_w);
    gemm_kernel<<<BB / BM, 512, GEMM_SMEM>>>(states);
    m_kernel<<<BB / MROWS, 256, M_SMEM>>>(v_w2, v_b2, out);
    attn_kernel<<<NB3, 256>>>(states, out);
    finalize_kernel<<<1, 256>>>(out);
}